// round 1
// baseline (speedup 1.0000x reference)
#include <cuda_runtime.h>
#include <cstdint>

namespace {

constexpr int CDIM = 256;       // embed dim
constexpr int FDIM = 512;       // ffn dim
constexpr int NDIM = 1024;      // sequence (n) length per slab
constexpr int TW = 64;          // tile width (positions per tile)
constexpr int NTILES = NDIM / TW;
constexpr int NTHREADS = 256;
constexpr int PD = 16;          // weight panel depth (k)
constexpr int CS = 4 * NDIM;    // channel stride in x (floats)
constexpr float EPS = 1e-5f;

struct Smem {
  float xt[CDIM * TW];      // x tile, later x2 tile
  float yt[CDIM * TW];      // y1 / attn / y2 tile
  float hbuf[64 * TW];      // FFN hidden block
  float wp[PD * CDIM];      // weight panel
  float meanA[NDIM];
  float rstdA[NDIM];
  float qA[NDIM];           // q, then u = softmax*rstd
  float g1[CDIM];
  float be1[CDIM];
  float g2v[CDIM];
  float be2[CDIM];
  float avec[CDIM];         // w_q * g1
  float ctxv[CDIM];
  float ybar[CDIM];
  float bvv[CDIM];          // v bias
  float bov[CDIM];          // out-proj bias
  float bf2v[CDIM];         // ffn2 bias
  float bf1v[FDIM];         // ffn1 bias
  float red[32 * 65];       // LN2 cross-thread reduction (padded stride 65)
  float m2s[TW];
  float r2s[TW];
  float scratch[40];
};

__device__ __forceinline__ float warpSum(float v) {
#pragma unroll
  for (int o = 16; o; o >>= 1) v += __shfl_xor_sync(0xffffffffu, v, o);
  return v;
}

__device__ __forceinline__ float blockSum(float v, float* scr) {
  v = warpSum(v);
  const int w = threadIdx.x >> 5;
  if ((threadIdx.x & 31) == 0) scr[w] = v;
  __syncthreads();
  if (threadIdx.x == 0) {
    float t = 0.f;
#pragma unroll
    for (int i = 0; i < NTHREADS / 32; i++) t += scr[i];
    scr[8] = t;
  }
  __syncthreads();
  float r = scr[8];
  __syncthreads();
  return r;
}

__device__ __forceinline__ float blockMax(float v, float* scr) {
#pragma unroll
  for (int o = 16; o; o >>= 1) v = fmaxf(v, __shfl_xor_sync(0xffffffffu, v, o));
  const int w = threadIdx.x >> 5;
  if ((threadIdx.x & 31) == 0) scr[w] = v;
  __syncthreads();
  if (threadIdx.x == 0) {
    float t = scr[0];
#pragma unroll
    for (int i = 1; i < NTHREADS / 32; i++) t = fmaxf(t, scr[i]);
    scr[8] = t;
  }
  __syncthreads();
  float r = scr[8];
  __syncthreads();
  return r;
}

// C[256 x TW] += W[256 x kdim](row-major, ld=ldw, cols kcol0..) @ Ys[kdim x TW]
// 8x8 register tile per thread, 16-deep smem weight panels.
__device__ __forceinline__ void gemm_R256(const float* __restrict__ Wg, int ldw,
                                          int kcol0, int kdim,
                                          const float* __restrict__ Ys,
                                          float (&acc)[8][8],
                                          float* __restrict__ wp) {
  const int tid = threadIdx.x;
  const int tr = tid >> 3, tc = tid & 7;
#pragma unroll 1
  for (int kk = 0; kk < kdim; kk += PD) {
    __syncthreads();
    {
      const float* p = Wg + (size_t)tid * ldw + kcol0 + kk;
#pragma unroll
      for (int q = 0; q < PD / 4; q++) {
        float4 w4 = *(const float4*)(p + q * 4);
        wp[(q * 4 + 0) * CDIM + tid] = w4.x;
        wp[(q * 4 + 1) * CDIM + tid] = w4.y;
        wp[(q * 4 + 2) * CDIM + tid] = w4.z;
        wp[(q * 4 + 3) * CDIM + tid] = w4.w;
      }
    }
    __syncthreads();
#pragma unroll 4
    for (int k = 0; k < PD; k++) {
      const float* wr = wp + k * CDIM + tr * 8;
      float4 w0 = *(const float4*)(wr);
      float4 w1 = *(const float4*)(wr + 4);
      const float* yr = Ys + (kk + k) * TW + tc * 8;
      float4 y0 = *(const float4*)(yr);
      float4 y1 = *(const float4*)(yr + 4);
      float wv[8] = {w0.x, w0.y, w0.z, w0.w, w1.x, w1.y, w1.z, w1.w};
      float yv[8] = {y0.x, y0.y, y0.z, y0.w, y1.x, y1.y, y1.z, y1.w};
#pragma unroll
      for (int i = 0; i < 8; i++)
#pragma unroll
        for (int j = 0; j < 8; j++) acc[i][j] = fmaf(wv[i], yv[j], acc[i][j]);
    }
  }
}

// C[64 x TW] += W[64 x 256](row-major, ld=256) @ Ys[256 x TW]
// 2x8 register tile per thread.
__device__ __forceinline__ void gemm_R64(const float* __restrict__ Wg,
                                         const float* __restrict__ Ys,
                                         float (&acc)[2][8],
                                         float* __restrict__ wp) {
  const int tid = threadIdx.x;
  const int tr = tid >> 3, tc = tid & 7;
#pragma unroll 1
  for (int kk = 0; kk < CDIM; kk += PD) {
    __syncthreads();
    if (tid < 64) {
      const float* p = Wg + (size_t)tid * CDIM + kk;
#pragma unroll
      for (int q = 0; q < PD / 4; q++) {
        float4 w4 = *(const float4*)(p + q * 4);
        wp[(q * 4 + 0) * 64 + tid] = w4.x;
        wp[(q * 4 + 1) * 64 + tid] = w4.y;
        wp[(q * 4 + 2) * 64 + tid] = w4.z;
        wp[(q * 4 + 3) * 64 + tid] = w4.w;
      }
    }
    __syncthreads();
#pragma unroll 4
    for (int k = 0; k < PD; k++) {
      float2 w2 = *(const float2*)(wp + k * 64 + tr * 2);
      const float* yr = Ys + (kk + k) * TW + tc * 8;
      float4 y0 = *(const float4*)(yr);
      float4 y1 = *(const float4*)(yr + 4);
      float yv[8] = {y0.x, y0.y, y0.z, y0.w, y1.x, y1.y, y1.z, y1.w};
#pragma unroll
      for (int j = 0; j < 8; j++) {
        acc[0][j] = fmaf(w2.x, yv[j], acc[0][j]);
        acc[1][j] = fmaf(w2.y, yv[j], acc[1][j]);
      }
    }
  }
}

__global__ void __launch_bounds__(NTHREADS, 1)
fused_block_kernel(const float* __restrict__ x,
                   const float* __restrict__ ln1_w, const float* __restrict__ ln1_b,
                   const float* __restrict__ qkv_w, const float* __restrict__ qkv_b,
                   const float* __restrict__ out_w, const float* __restrict__ out_b,
                   const float* __restrict__ ln2_w, const float* __restrict__ ln2_b,
                   const float* __restrict__ ffn1_w, const float* __restrict__ ffn1_b,
                   const float* __restrict__ ffn2_w, const float* __restrict__ ffn2_b,
                   float* __restrict__ out) {
  extern __shared__ __align__(16) char smem_raw[];
  Smem* s = reinterpret_cast<Smem*>(smem_raw);
  const int tid = threadIdx.x;
  const int b = blockIdx.x >> 2;
  const int p = blockIdx.x & 3;
  const size_t base = (size_t)b * (CDIM * 4 * NDIM) + (size_t)p * NDIM;

  // ---------- Phase 0: cache small vectors ----------
  for (int i = tid; i < CDIM; i += NTHREADS) {
    float g = ln1_w[i];
    s->g1[i] = g;
    s->be1[i] = ln1_b[i];
    s->g2v[i] = ln2_w[i];
    s->be2[i] = ln2_b[i];
    s->avec[i] = qkv_w[i] * g;              // row 0 of qkv_w = w_q
    s->bvv[i] = qkv_b[1 + CDIM + i];
    s->bov[i] = out_b[i];
    s->bf2v[i] = ffn2_b[i];
  }
  for (int i = tid; i < FDIM; i += NTHREADS) s->bf1v[i] = ffn1_b[i];
  float aP = 0.f, bP = 0.f;
  for (int i = tid; i < CDIM; i += NTHREADS) {
    aP += qkv_w[i] * ln1_w[i];
    bP += qkv_w[i] * ln1_b[i];
  }
  __syncthreads();
  const float A_ = blockSum(aP, s->scratch);
  const float B0_ = blockSum(bP, s->scratch) + qkv_b[0];

  // ---------- Phase 1: LN stats + q per column ----------
#pragma unroll 1
  for (int pass = 0; pass < NDIM / NTHREADS; pass++) {
    const int n = pass * NTHREADS + tid;
    const float* xp = x + base + n;
    float s1 = 0.f, s2 = 0.f, sq = 0.f;
#pragma unroll 8
    for (int c = 0; c < CDIM; c++) {
      float v = __ldg(xp + (size_t)c * CS);
      s1 += v;
      s2 = fmaf(v, v, s2);
      sq = fmaf(s->avec[c], v, sq);
    }
    const float mean = s1 * (1.0f / 256.0f);
    const float var = s2 * (1.0f / 256.0f) - mean * mean;
    const float rstd = rsqrtf(var + EPS);
    s->meanA[n] = mean;
    s->rstdA[n] = rstd;
    s->qA[n] = rstd * (sq - mean * A_) + B0_;
  }
  __syncthreads();

  // ---------- Phase 2: softmax over n, ybar, ctx ----------
  {
    float mx = -3.4e38f;
#pragma unroll
    for (int k = 0; k < 4; k++) mx = fmaxf(mx, s->qA[k * NTHREADS + tid]);
    mx = blockMax(mx, s->scratch);
    float ev[4];
    float ssum = 0.f, usum = 0.f;
#pragma unroll
    for (int k = 0; k < 4; k++) {
      const int i = k * NTHREADS + tid;
      float e = expf(s->qA[i] - mx);
      ev[k] = e;
      ssum += e;
      usum = fmaf(e, s->rstdA[i] * s->meanA[i], usum);
    }
    ssum = blockSum(ssum, s->scratch);
    usum = blockSum(usum, s->scratch);
    const float inv = 1.0f / ssum;
    const float U = usum * inv;
#pragma unroll
    for (int k = 0; k < 4; k++) {
      const int i = k * NTHREADS + tid;
      s->qA[i] = ev[k] * inv * s->rstdA[i];   // u_n = softmax_n * rstd_n
    }
    __syncthreads();

    const int w = tid >> 5, l = tid & 31;
    // ybar_c = g1_c * (X_row_c . u - U) + be1_c
    for (int r = w; r < CDIM; r += 8) {
      const float* xr = x + base + (size_t)r * CS;
      float acc = 0.f;
#pragma unroll 4
      for (int i = l; i < NDIM; i += 32) acc = fmaf(__ldg(xr + i), s->qA[i], acc);
      acc = warpSum(acc);
      if (l == 0) s->ybar[r] = s->g1[r] * (acc - U) + s->be1[r];
    }
    __syncthreads();
    // ctx = W_k @ ybar + b_k   (rows 1..256 of qkv)
    for (int r = w; r < CDIM; r += 8) {
      const float* wr = qkv_w + (size_t)(1 + r) * CDIM;
      float acc = 0.f;
#pragma unroll 4
      for (int i = l; i < CDIM; i += 32) acc = fmaf(__ldg(wr + i), s->ybar[i], acc);
      acc = warpSum(acc);
      if (l == 0) s->ctxv[r] = acc + qkv_b[1 + r];
    }
    __syncthreads();
  }

  // ---------- Phase 3: tiled main pipeline ----------
  const int tr = tid >> 3, tc = tid & 7;
#pragma unroll 1
  for (int it = 0; it < NTILES; it++) {
    const int n0 = it * TW;

    // load x tile + build y1 tile
    for (int idx = tid; idx < CDIM * (TW / 4); idx += NTHREADS) {
      const int r = idx >> 4;
      const int j = (idx & 15) << 2;
      float4 xv = *(const float4*)(x + base + (size_t)r * CS + n0 + j);
      *(float4*)&s->xt[r * TW + j] = xv;
      float4 mv = *(const float4*)&s->meanA[n0 + j];
      float4 rv = *(const float4*)&s->rstdA[n0 + j];
      const float g = s->g1[r], be = s->be1[r];
      float4 yv;
      yv.x = (xv.x - mv.x) * rv.x * g + be;
      yv.y = (xv.y - mv.y) * rv.y * g + be;
      yv.z = (xv.z - mv.z) * rv.z * g + be;
      yv.w = (xv.w - mv.w) * rv.w * g + be;
      *(float4*)&s->yt[r * TW + j] = yv;
    }

    float acc[8][8];
#pragma unroll
    for (int i = 0; i < 8; i++)
#pragma unroll
      for (int j = 0; j < 8; j++) acc[i][j] = 0.f;

    // G1: V = W_v @ Y1   (rows 257..512 of qkv)
    gemm_R256(qkv_w + (size_t)(1 + CDIM) * CDIM, CDIM, 0, CDIM, s->yt, acc, s->wp);
    __syncthreads();  // all reads of yt done before overwrite
#pragma unroll
    for (int i = 0; i < 8; i++) {
      const int r = tr * 8 + i;
      const float bv = s->bvv[r], cx = s->ctxv[r];
      float4 o0, o1;
      o0.x = fmaxf(acc[i][0] + bv, 0.f) * cx;
      o0.y = fmaxf(acc[i][1] + bv, 0.f) * cx;
      o0.z = fmaxf(acc[i][2] + bv, 0.f) * cx;
      o0.w = fmaxf(acc[i][3] + bv, 0.f) * cx;
      o1.x = fmaxf(acc[i][4] + bv, 0.f) * cx;
      o1.y = fmaxf(acc[i][5] + bv, 0.f) * cx;
      o1.z = fmaxf(acc[i][6] + bv, 0.f) * cx;
      o1.w = fmaxf(acc[i][7] + bv, 0.f) * cx;
      *(float4*)&s->yt[r * TW + tc * 8] = o0;
      *(float4*)&s->yt[r * TW + tc * 8 + 4] = o1;
    }

#pragma unroll
    for (int i = 0; i < 8; i++)
#pragma unroll
      for (int j = 0; j < 8; j++) acc[i][j] = 0.f;

    // G2: O = W_out @ attn ; x2 = x + O + b ; LN2 partials in registers
    gemm_R256(out_w, CDIM, 0, CDIM, s->yt, acc, s->wp);
    __syncthreads();
    float s1l[8], s2l[8];
#pragma unroll
    for (int j = 0; j < 8; j++) { s1l[j] = 0.f; s2l[j] = 0.f; }
#pragma unroll
    for (int i = 0; i < 8; i++) {
      const int r = tr * 8 + i;
      const float bo = s->bov[r];
      float4 xa = *(const float4*)&s->xt[r * TW + tc * 8];
      float4 xb = *(const float4*)&s->xt[r * TW + tc * 8 + 4];
      float xs[8] = {xa.x, xa.y, xa.z, xa.w, xb.x, xb.y, xb.z, xb.w};
#pragma unroll
      for (int j = 0; j < 8; j++) {
        const float v = acc[i][j] + bo + xs[j];
        acc[i][j] = v;                      // acc now holds x2
        s1l[j] += v;
        s2l[j] = fmaf(v, v, s2l[j]);
      }
      float4 w0 = {acc[i][0], acc[i][1], acc[i][2], acc[i][3]};
      float4 w1 = {acc[i][4], acc[i][5], acc[i][6], acc[i][7]};
      *(float4*)&s->xt[r * TW + tc * 8] = w0;     // xt now holds x2
      *(float4*)&s->xt[r * TW + tc * 8 + 4] = w1;
    }
    // LN2 stats: reduce 32 row-group partials per column
#pragma unroll
    for (int j = 0; j < 8; j++) s->red[tr * 65 + tc * 8 + j] = s1l[j];
    __syncthreads();
    {
      const int w = tid >> 5, l = tid & 31;
#pragma unroll
      for (int cc = 0; cc < 8; cc++) {
        const int col = w * 8 + cc;
        float v = warpSum(s->red[l * 65 + col]);
        if (l == 0) s->m2s[col] = v * (1.0f / 256.0f);
      }
    }
    __syncthreads();
#pragma unroll
    for (int j = 0; j < 8; j++) s->red[tr * 65 + tc * 8 + j] = s2l[j];
    __syncthreads();
    {
      const int w = tid >> 5, l = tid & 31;
#pragma unroll
      for (int cc = 0; cc < 8; cc++) {
        const int col = w * 8 + cc;
        float v = warpSum(s->red[l * 65 + col]);
        if (l == 0) {
          const float m = s->m2s[col];
          s->r2s[col] = rsqrtf(v * (1.0f / 256.0f) - m * m + EPS);
        }
      }
    }
    __syncthreads();
    // y2 into yt (from x2 held in registers)
#pragma unroll
    for (int i = 0; i < 8; i++) {
      const int r = tr * 8 + i;
      const float g = s->g2v[r], be = s->be2[r];
      float4 y0, y1;
      y0.x = (acc[i][0] - s->m2s[tc * 8 + 0]) * s->r2s[tc * 8 + 0] * g + be;
      y0.y = (acc[i][1] - s->m2s[tc * 8 + 1]) * s->r2s[tc * 8 + 1] * g + be;
      y0.z = (acc[i][2] - s->m2s[tc * 8 + 2]) * s->r2s[tc * 8 + 2] * g + be;
      y0.w = (acc[i][3] - s->m2s[tc * 8 + 3]) * s->r2s[tc * 8 + 3] * g + be;
      y1.x = (acc[i][4] - s->m2s[tc * 8 + 4]) * s->r2s[tc * 8 + 4] * g + be;
      y1.y = (acc[i][5] - s->m2s[tc * 8 + 5]) * s->r2s[tc * 8 + 5] * g + be;
      y1.z = (acc[i][6] - s->m2s[tc * 8 + 6]) * s->r2s[tc * 8 + 6] * g + be;
      y1.w = (acc[i][7] - s->m2s[tc * 8 + 7]) * s->r2s[tc * 8 + 7] * g + be;
      *(float4*)&s->yt[r * TW + tc * 8] = y0;
      *(float4*)&s->yt[r * TW + tc * 8 + 4] = y1;
    }

    // FFN: H in 64-row blocks, G4 accumulates across blocks
    float accR[8][8];
#pragma unroll
    for (int i = 0; i < 8; i++)
#pragma unroll
      for (int j = 0; j < 8; j++) accR[i][j] = 0.f;

#pragma unroll 1
    for (int hb = 0; hb < FDIM / 64; hb++) {
      float a3[2][8];
#pragma unroll
      for (int i = 0; i < 2; i++)
#pragma unroll
        for (int j = 0; j < 8; j++) a3[i][j] = 0.f;
      gemm_R64(ffn1_w + (size_t)hb * 64 * CDIM, s->yt, a3, s->wp);
      __syncthreads();
#pragma unroll
      for (int i = 0; i < 2; i++) {
        const int hr = tr * 2 + i;
        const float bf = s->bf1v[hb * 64 + hr];
        float hv[8];
#pragma unroll
        for (int j = 0; j < 8; j++) {
          float h = a3[i][j] + bf;
          hv[j] = (h > 0.f) ? h : 0.1f * h;   // leaky_relu 0.1
        }
        float4 h0 = {hv[0], hv[1], hv[2], hv[3]};
        float4 h1 = {hv[4], hv[5], hv[6], hv[7]};
        *(float4*)&s->hbuf[hr * TW + tc * 8] = h0;
        *(float4*)&s->hbuf[hr * TW + tc * 8 + 4] = h1;
      }
      // G4 partial: accR += W2[:, hb*64 .. +64] @ Hblk
      gemm_R256(ffn2_w, FDIM, hb * 64, 64, s->hbuf, accR, s->wp);
    }

    // final epilogue: out = x2 + W2@H + b2
    __syncthreads();
#pragma unroll
    for (int i = 0; i < 8; i++) {
      const int r = tr * 8 + i;
      const float bf = s->bf2v[r];
      float4 xa = *(const float4*)&s->xt[r * TW + tc * 8];
      float4 xb = *(const float4*)&s->xt[r * TW + tc * 8 + 4];
      float4 o0, o1;
      o0.x = accR[i][0] + bf + xa.x;
      o0.y = accR[i][1] + bf + xa.y;
      o0.z = accR[i][2] + bf + xa.z;
      o0.w = accR[i][3] + bf + xa.w;
      o1.x = accR[i][4] + bf + xb.x;
      o1.y = accR[i][5] + bf + xb.y;
      o1.z = accR[i][6] + bf + xb.z;
      o1.w = accR[i][7] + bf + xb.w;
      float* op = out + base + (size_t)r * CS + n0 + tc * 8;
      *(float4*)op = o0;
      *(float4*)(op + 4) = o1;
    }
    __syncthreads();  // protect xt/yt/red reuse next tile
  }
}

}  // namespace

extern "C" void kernel_launch(void* const* d_in, const int* in_sizes, int n_in,
                              void* d_out, int out_size) {
  const float* x      = (const float*)d_in[0];
  const float* ln1_w  = (const float*)d_in[1];
  const float* ln1_b  = (const float*)d_in[2];
  const float* qkv_w  = (const float*)d_in[3];
  const float* qkv_b  = (const float*)d_in[4];
  const float* out_w  = (const float*)d_in[5];
  const float* out_b  = (const float*)d_in[6];
  const float* ln2_w  = (const float*)d_in[7];
  const float* ln2_b  = (const float*)d_in[8];
  const float* ffn1_w = (const float*)d_in[9];
  const float* ffn1_b = (const float*)d_in[10];
  const float* ffn2_w = (const float*)d_in[11];
  const float* ffn2_b = (const float*)d_in[12];
  float* out = (float*)d_out;

  const int B = in_sizes[0] / (CDIM * 4 * NDIM);
  const int grid = B * 4;
  const int smem = (int)sizeof(Smem);
  cudaFuncSetAttribute(fused_block_kernel,
                       cudaFuncAttributeMaxDynamicSharedMemorySize, smem);
  fused_block_kernel<<<grid, NTHREADS, smem>>>(
      x, ln1_w, ln1_b, qkv_w, qkv_b, out_w, out_b, ln2_w, ln2_b,
      ffn1_w, ffn1_b, ffn2_w, ffn2_b, out);
}